// round 4
// baseline (speedup 1.0000x reference)
#include <cuda_runtime.h>
#include <cstdint>
#include <math.h>

#define B_   128
#define N_   8
#define LQ   32
#define LD   256
#define D_   128
#define NEGV (-9999.0f)
#define SMEM_BYTES 83600

__device__ float g_scores[2 * N_ * B_];   // [z][n][b]

// ---- packed f32x2 helpers (FFMA2 — only reachable via explicit PTX) ----
__device__ __forceinline__ void ffma2(unsigned long long& c, unsigned long long a,
                                      unsigned long long b) {
    asm("fma.rn.f32x2 %0, %1, %2, %0;" : "+l"(c) : "l"(a), "l"(b));
}
__device__ __forceinline__ float hsum2(unsigned long long c) {
    return __uint_as_float((unsigned)c) + __uint_as_float((unsigned)(c >> 32));
}
__device__ __forceinline__ void cp16(uint32_t dst, const void* src) {
    asm volatile("cp.async.cg.shared.global [%0], [%1], 16;" :: "r"(dst), "l"(src));
}
__device__ __forceinline__ void cp_commit() {
    asm volatile("cp.async.commit_group;");
}
template <int N>
__device__ __forceinline__ void cp_wait() {
    asm volatile("cp.async.wait_group %0;" :: "n"(N));
}

// ---------------------------------------------------------------------------
// MaxSim: grid (B, N, 2), 128 threads, 2 CTAs/SM.
// cp.async double-buffered 64-row x 128-k tiles; 4 warps = 2 row-halves x
// 2 q-halves; per thread 4r x 4q full-K FFMA2 tile. Norms folded post-GEMM.
// ---------------------------------------------------------------------------
__global__ void __launch_bounds__(128, 2)
maxsim_kernel(const float* __restrict__ q, const float* __restrict__ dcq,
              const float* __restrict__ dorig, const int* __restrict__ mask)
{
    extern __shared__ float4 smem4[];
    float4* sD0  = smem4;                  // buf0: 64 rows x 32 quads (32 KB)
    float4* sQ4  = smem4 + 4096;           // 32 rows x 32 quads (16 KB)
    float*  tail = (float*)(smem4 + 5120);
    float*  sInvQ = tail;                  // 32
    float*  sInvD = tail + 32;             // 64
    float*  sP    = tail + 96;             // 64
    int*    sAct  = (int*)(tail + 160);    // 256
    int*    sCnt  = (int*)(tail + 416);

    const int b = blockIdx.x, n = blockIdx.y, z = blockIdx.z;
    const int t = threadIdx.x;
    const int lane = t & 31, w = t >> 5;
    const float* __restrict__ dpair = (z ? dorig : dcq) + (size_t)(n * B_ + b) * (LD * D_);

    if (t == 0) *sCnt = 0;
    __syncthreads();

    // ---- q tile: swizzled store + per-row inverse norm ----
    {
        const float4* qsrc = (const float4*)(q + (size_t)b * LQ * D_);
#pragma unroll
        for (int it = 0; it < 8; it++) {
            int row = it * 4 + w;                    // one row per warp per it
            float4 v = qsrc[it * 128 + t];
            sQ4[row * 32 + (lane ^ ((row >> 2) & 7))] = v;
            float ss = v.x * v.x + v.y * v.y + v.z * v.z + v.w * v.w;
#pragma unroll
            for (int o = 16; o; o >>= 1) ss += __shfl_xor_sync(~0u, ss, o);
            if (lane == 0) sInvQ[row] = 1.0f / fmaxf(sqrtf(ss), 1e-12f);
        }
    }

    // ---- mask compaction (order irrelevant: max is commutative) ----
#pragma unroll
    for (int i = t; i < LD; i += 128)
        if (mask[(n * B_ + b) * LD + i]) sAct[atomicAdd(sCnt, 1)] = i;
    __syncthreads();
    const int cnt = *sCnt;
    if (cnt == 0) {                        // all masked: scores = 32 * NEG
        if (t == 0) g_scores[(z * N_ + n) * B_ + b] = 32.0f * NEGV;
        return;
    }
    const int nch = (cnt + 63) >> 6;

    // ---- thread geometry ----
    const int wr  = w >> 1;                // row half (32 rows)
    const int wq  = w & 1;                 // query half (16 q)
    const int rgl = lane >> 2;             // 8 row groups
    const int qgl = lane & 3;              // 4 query groups
    const int row0 = 32 * wr + 4 * rgl;
    const int q0   = 16 * wq + 4 * qgl;
    const int qxor = (4 * wq + qgl) & 7;   // == (qrow>>2)&7 for this thread's queries
    const uint32_t sD0a = (uint32_t)__cvta_generic_to_shared(sD0);

    float mx[4] = {-1e30f, -1e30f, -1e30f, -1e30f};

    // ---- prologue: issue chunk 0 into buf 0 (tails duplicate a valid row) ----
    {
#pragma unroll
        for (int it = 0; it < 16; it++) {
            int row = it * 4 + w;
            int idx = row; if (idx >= cnt) idx = cnt - 1;
            const void* src = dpair + sAct[idx] * D_ + lane * 4;
            uint32_t dst = sD0a + (uint32_t)((row * 32 + (lane ^ ((row >> 2) & 7))) * 16);
            cp16(dst, src);
        }
        cp_commit();
    }

    for (int ch = 0; ch < nch; ch++) {
        // ---- prefetch next chunk into other buffer ----
        if (ch + 1 < nch) {
            uint32_t basea = sD0a + (uint32_t)(((ch + 1) & 1) * 32768);
#pragma unroll
            for (int it = 0; it < 16; it++) {
                int row = it * 4 + w;
                int idx = (ch + 1) * 64 + row; if (idx >= cnt) idx = cnt - 1;
                const void* src = dpair + sAct[idx] * D_ + lane * 4;
                uint32_t dst = basea + (uint32_t)((row * 32 + (lane ^ ((row >> 2) & 7))) * 16);
                cp16(dst, src);
            }
            cp_commit();
            cp_wait<1>();
        } else {
            cp_wait<0>();
        }
        __syncthreads();   // tile (ch) visible to all

        const float4* __restrict__ sDb = sD0 + (ch & 1) * 2048;

        // ---- row norms: permutation-invariant, read physical quads ----
        {
#pragma unroll
            for (int rr = 0; rr < 16; rr++) {
                int row = w * 16 + rr;
                float4 v = sDb[row * 32 + lane];
                float ss = v.x * v.x + v.y * v.y + v.z * v.z + v.w * v.w;
#pragma unroll
                for (int o = 16; o; o >>= 1) ss += __shfl_xor_sync(~0u, ss, o);
                if (lane == 0) sInvD[row] = 1.0f / fmaxf(sqrtf(ss), 1e-12f);
            }
        }
        __syncthreads();   // sInvD visible

        // ---- GEMM: full K = 32 quads ----
        unsigned long long acc[16];
#pragma unroll
        for (int i = 0; i < 16; i++) acc[i] = 0ull;

#pragma unroll 4
        for (int kq = 0; kq < 32; kq++) {
            ulonglong2 qv[4], dv[4];
#pragma unroll
            for (int i = 0; i < 4; i++)
                qv[i] = *(const ulonglong2*)(sQ4 + (q0 + i) * 32 + (kq ^ qxor));
#pragma unroll
            for (int i = 0; i < 4; i++)
                dv[i] = *(const ulonglong2*)(sDb + (row0 + i) * 32 + (kq ^ rgl));
#pragma unroll
            for (int qi = 0; qi < 4; qi++)
#pragma unroll
                for (int ri = 0; ri < 4; ri++) {
                    ffma2(acc[qi * 4 + ri], dv[ri].x, qv[qi].x);
                    ffma2(acc[qi * 4 + ri], dv[ri].y, qv[qi].y);
                }
        }

        // ---- epilogue: scale by 1/||d||, fold into running max ----
#pragma unroll
        for (int qi = 0; qi < 4; qi++)
#pragma unroll
            for (int ri = 0; ri < 4; ri++) {
                float val = hsum2(acc[qi * 4 + ri]) * sInvD[row0 + ri];
                mx[qi] = fmaxf(mx[qi], val);
            }
        __syncthreads();   // done reading sDb/sInvD before next overwrite
    }

    // ---- max over row groups within warp (lanes stride 4) ----
#pragma unroll
    for (int qi = 0; qi < 4; qi++) {
#pragma unroll
        for (int o = 16; o >= 4; o >>= 1)
            mx[qi] = fmaxf(mx[qi], __shfl_xor_sync(~0u, mx[qi], o));
    }
    if (lane < 4) {
#pragma unroll
        for (int qi = 0; qi < 4; qi++) sP[w * 16 + lane * 4 + qi] = mx[qi];
    }
    __syncthreads();

    // ---- combine row-halves, scale by 1/||q||, sum over 32 queries ----
    if (t < 32) {
        int wq2 = t >> 4, qg2 = (t >> 2) & 3, qq2 = t & 3;
        float v = fmaxf(sP[(0 * 2 + wq2) * 16 + qg2 * 4 + qq2],
                        sP[(1 * 2 + wq2) * 16 + qg2 * 4 + qq2]) * sInvQ[t];
#pragma unroll
        for (int o = 16; o; o >>= 1) v += __shfl_xor_sync(~0u, v, o);
        if (t == 0) g_scores[(z * N_ + n) * B_ + b] = v;
    }
}

// ---------------------------------------------------------------------------
// KL(batchmean) over [B, N]
// ---------------------------------------------------------------------------
__global__ void __launch_bounds__(128) loss_kernel(float* __restrict__ out)
{
    int b = threadIdx.x;
    float s[N_], tt[N_];
#pragma unroll
    for (int n = 0; n < N_; n++) {
        s[n]  = g_scores[n * B_ + b];
        tt[n] = g_scores[(N_ + n) * B_ + b];
    }
    float ms = s[0], mt = tt[0];
#pragma unroll
    for (int n = 1; n < N_; n++) { ms = fmaxf(ms, s[n]); mt = fmaxf(mt, tt[n]); }
    float es = 0.f, et = 0.f;
#pragma unroll
    for (int n = 0; n < N_; n++) { es += expf(s[n] - ms); et += expf(tt[n] - mt); }
    float lses = ms + logf(es);
    float lset = mt + logf(et);
    float kl = 0.f;
#pragma unroll
    for (int n = 0; n < N_; n++) {
        float lt = tt[n] - lset;
        float ls = s[n]  - lses;
        kl += expf(lt) * (lt - ls);
    }
    __shared__ float red[128];
    red[b] = kl;
    __syncthreads();
#pragma unroll
    for (int o = 64; o; o >>= 1) {
        if (b < o) red[b] += red[b + o];
        __syncthreads();
    }
    if (b == 0) out[0] = red[0] / (float)B_;
}

// ---------------------------------------------------------------------------
extern "C" void kernel_launch(void* const* d_in, const int* in_sizes, int n_in,
                              void* d_out, int out_size)
{
    const float* q     = (const float*)d_in[0];   // [B,Lq,D]
    const float* dcq   = (const float*)d_in[1];   // [N,B,Ld,D]
    const float* dorig = (const float*)d_in[2];   // [N,B,Ld,D]
    const int*   mask  = (const int*)d_in[3];     // [N,B,Ld]

    cudaFuncSetAttribute(maxsim_kernel,
                         cudaFuncAttributeMaxDynamicSharedMemorySize, SMEM_BYTES);
    dim3 grid(B_, N_, 2);
    maxsim_kernel<<<grid, 128, SMEM_BYTES>>>(q, dcq, dorig, mask);
    loss_kernel<<<1, 128>>>((float*)d_out);
}

// round 9
// speedup vs baseline: 1.4611x; 1.4611x over previous
#include <cuda_runtime.h>
#include <cstdint>
#include <math.h>

#define B_   128
#define N_   8
#define LQ   32
#define LD   256
#define D_   128
#define NEGV (-9999.0f)
#define STRD 132                       // padded row stride (floats): conflict-free frag loads

// ---- dynamic smem layout (bytes) ----
#define D0_OFF  0                       // chunk buf 0: 64 rows x 132 floats (raw fp32)
#define D1_OFF  33792
#define QH_OFF  67584                   // Q hi tile: 32 rows x 132 floats (tf32-valued)
#define QL_OFF  (QH_OFF + 16896)        // Q lo tile
#define INV_OFF (QL_OFF + 16896)        // 64 floats: per-row 1/||d||
#define W_OFF   (INV_OFF + 256)         // 128 floats: per-warp query maxima
#define ACT_OFF (W_OFF + 512)           // 256 ints: compacted row ids
#define CNT_OFF (ACT_OFF + 1024)
#define SMEM_TOTAL (CNT_OFF + 16)       // 103200 B; x2 CTA/SM = 206.4 KB < 228 KB

__device__ float g_scores[2 * N_ * B_];   // [z][n][b]

__device__ __forceinline__ uint32_t smem_u32(const void* p) {
    uint32_t a;
    asm("{ .reg .u64 t; cvta.to.shared.u64 t, %1; cvt.u32.u64 %0, t; }" : "=r"(a) : "l"(p));
    return a;
}
__device__ __forceinline__ void cp16(uint32_t dst, const void* src) {
    asm volatile("cp.async.cg.shared.global [%0], [%1], 16;" :: "r"(dst), "l"(src));
}
__device__ __forceinline__ void cp_commit() { asm volatile("cp.async.commit_group;"); }
template<int NN> __device__ __forceinline__ void cp_wait() {
    asm volatile("cp.async.wait_group %0;" :: "n"(NN));
}
__device__ __forceinline__ uint32_t to_tf32(float f) {
    uint32_t r;
    asm("cvt.rna.tf32.f32 %0, %1;" : "=r"(r) : "f"(f));
    return r;
}
// m16n8k8 tf32 MMA (sm_80+ ISA; works on plain compute_100)
__device__ __forceinline__ void mma_tf32(float* c, const uint32_t* a,
                                         uint32_t b0, uint32_t b1) {
    asm volatile(
        "mma.sync.aligned.m16n8k8.row.col.f32.tf32.tf32.f32 "
        "{%0,%1,%2,%3}, {%4,%5,%6,%7}, {%8,%9}, {%0,%1,%2,%3};"
        : "+f"(c[0]), "+f"(c[1]), "+f"(c[2]), "+f"(c[3])
        : "r"(a[0]), "r"(a[1]), "r"(a[2]), "r"(a[3]), "r"(b0), "r"(b1));
}

// ---------------------------------------------------------------------------
// MaxSim: grid (B, N, 2), 256 threads (8 warps), 2 CTAs/SM.
// 3xTF32 error-compensated MMA: acc = Ah*Bh + Ah*Bl + Al*Bh (rel err ~2^-22).
// 8 warps = 2 q-halves x 4 row-groups. Mask compaction; 64-row chunks,
// cp.async double-buffered; fp32 row norms folded post-GEMM; running max.
// ---------------------------------------------------------------------------
__global__ void __launch_bounds__(256, 2)
maxsim_mma(const float* __restrict__ q, const float* __restrict__ dcq,
           const float* __restrict__ dorig, const int* __restrict__ mask)
{
    extern __shared__ __align__(16) char smem[];
    const uint32_t sbu = smem_u32(smem);
    float* sQh  = (float*)(smem + QH_OFF);
    float* sQl  = (float*)(smem + QL_OFF);
    float* sInv = (float*)(smem + INV_OFF);
    float* sW   = (float*)(smem + W_OFF);
    int*   sAct = (int*)(smem + ACT_OFF);
    int*   sCnt = (int*)(smem + CNT_OFF);

    const int b = blockIdx.x, n = blockIdx.y, z = blockIdx.z;
    const int t = threadIdx.x, lane = t & 31, w = t >> 5;
    const int wq = w & 1, wn = w >> 1;
    const float* __restrict__ dpair = (z ? dorig : dcq) + (size_t)(n * B_ + b) * (LD * D_);

    if (t == 0) *sCnt = 0;

    // ---- stage Q: fp32 normalize, split hi/lo, store padded rows ----
    {
        const float4* qb = (const float4*)(q + (size_t)b * LQ * D_);
#pragma unroll
        for (int it = 0; it < 4; it++) {
            int row = it * 8 + w;
            float4 v = qb[row * 32 + lane];
            float ss = v.x * v.x + v.y * v.y + v.z * v.z + v.w * v.w;
#pragma unroll
            for (int o = 16; o; o >>= 1) ss += __shfl_xor_sync(~0u, ss, o);
            float inv = 1.0f / fmaxf(sqrtf(ss), 1e-12f);
            v.x *= inv; v.y *= inv; v.z *= inv; v.w *= inv;
            float4 hi, lo;
            hi.x = __uint_as_float(to_tf32(v.x)); lo.x = __uint_as_float(to_tf32(v.x - hi.x));
            hi.y = __uint_as_float(to_tf32(v.y)); lo.y = __uint_as_float(to_tf32(v.y - hi.y));
            hi.z = __uint_as_float(to_tf32(v.z)); lo.z = __uint_as_float(to_tf32(v.z - hi.z));
            hi.w = __uint_as_float(to_tf32(v.w)); lo.w = __uint_as_float(to_tf32(v.w - hi.w));
            *(float4*)(sQh + row * STRD + lane * 4) = hi;
            *(float4*)(sQl + row * STRD + lane * 4) = lo;
        }
    }
    __syncthreads();

    // ---- mask compaction (order irrelevant: max is commutative) ----
    if (mask[(n * B_ + b) * LD + t]) sAct[atomicAdd(sCnt, 1)] = t;
    __syncthreads();
    const int cnt = *sCnt;
    if (cnt == 0) {                         // all masked: scores = 32 * NEG
        if (t == 0) g_scores[(z * N_ + n) * B_ + b] = 32.0f * NEGV;
        return;
    }
    const int nch = (cnt + 63) >> 6;

    auto load_chunk = [&](int ch) {
        uint32_t dstb = sbu + ((ch & 1) ? D1_OFF : D0_OFF);
#pragma unroll
        for (int it = 0; it < 8; it++) {
            int row = it * 8 + w;
            int idx = ch * 64 + row; if (idx >= cnt) idx = cnt - 1;  // pad: dup valid row
            cp16(dstb + (uint32_t)((row * STRD + lane * 4) * 4),
                 dpair + (size_t)sAct[idx] * D_ + lane * 4);
        }
    };

    load_chunk(0); cp_commit();

    // fragment base pointers
    const int aoff = (16 * wq + (lane >> 2)) * STRD + (lane & 3);
    const float* Ah = sQh + aoff;
    const float* Al = sQl + aoff;
    const int    nb0 = 16 * wn + (lane >> 2);
    float mx0 = -1e30f, mx1 = -1e30f;

    for (int ch = 0; ch < nch; ch++) {
        if (ch + 1 < nch) load_chunk(ch + 1);
        cp_commit();
        if (ch + 1 < nch) { cp_wait<1>(); } else { cp_wait<0>(); }
        __syncthreads();                       // chunk ch resident everywhere

        float* Db = (float*)(smem + ((ch & 1) ? D1_OFF : D0_OFF));

        // ---- per-row inverse norms (fp32 exact) ----
#pragma unroll
        for (int rr = 0; rr < 8; rr++) {
            int row = w * 8 + rr;
            float4 v = *(const float4*)(Db + row * STRD + lane * 4);
            float ss = v.x * v.x + v.y * v.y + v.z * v.z + v.w * v.w;
#pragma unroll
            for (int o = 16; o; o >>= 1) ss += __shfl_xor_sync(~0u, ss, o);
            if (lane == 0) sInv[row] = 1.0f / fmaxf(sqrtf(ss), 1e-12f);
        }
        __syncthreads();

        // ---- 3xTF32 MMA k-loop: 16 steps of k8; 2 n8 tiles ----
        float acc0[4] = {0.f, 0.f, 0.f, 0.f};
        float acc1[4] = {0.f, 0.f, 0.f, 0.f};
        const float* Brow0 = Db + nb0 * STRD + (lane & 3);
        const float* Brow1 = Brow0 + 8 * STRD;

#pragma unroll
        for (int s = 0; s < 16; s++) {
            const int k0 = 8 * s;
            uint32_t ah[4], al[4];
            ah[0] = __float_as_uint(Ah[k0]);
            ah[1] = __float_as_uint(Ah[8 * STRD + k0]);
            ah[2] = __float_as_uint(Ah[k0 + 4]);
            ah[3] = __float_as_uint(Ah[8 * STRD + k0 + 4]);
            al[0] = __float_as_uint(Al[k0]);
            al[1] = __float_as_uint(Al[8 * STRD + k0]);
            al[2] = __float_as_uint(Al[k0 + 4]);
            al[3] = __float_as_uint(Al[8 * STRD + k0 + 4]);

            // tile 0
            {
                float b0 = Brow0[k0], b1 = Brow0[k0 + 4];
                uint32_t b0h = to_tf32(b0), b1h = to_tf32(b1);
                uint32_t b0l = to_tf32(b0 - __uint_as_float(b0h));
                uint32_t b1l = to_tf32(b1 - __uint_as_float(b1h));
                mma_tf32(acc0, ah, b0h, b1h);
                mma_tf32(acc0, ah, b0l, b1l);
                mma_tf32(acc0, al, b0h, b1h);
            }
            // tile 1
            {
                float c0 = Brow1[k0], c1 = Brow1[k0 + 4];
                uint32_t c0h = to_tf32(c0), c1h = to_tf32(c1);
                uint32_t c0l = to_tf32(c0 - __uint_as_float(c0h));
                uint32_t c1l = to_tf32(c1 - __uint_as_float(c1h));
                mma_tf32(acc1, ah, c0h, c1h);
                mma_tf32(acc1, ah, c0l, c1l);
                mma_tf32(acc1, al, c0h, c1h);
            }
        }

        // ---- epilogue: scale by 1/||d||, fold into running per-query max ----
        float2 i0 = *(const float2*)(sInv + 16 * wn + 2 * (lane & 3));
        float2 i1 = *(const float2*)(sInv + 16 * wn + 8 + 2 * (lane & 3));
        mx0 = fmaxf(mx0, fmaxf(fmaxf(acc0[0] * i0.x, acc0[1] * i0.y),
                               fmaxf(acc1[0] * i1.x, acc1[1] * i1.y)));
        mx1 = fmaxf(mx1, fmaxf(fmaxf(acc0[2] * i0.x, acc0[3] * i0.y),
                               fmaxf(acc1[2] * i1.x, acc1[3] * i1.y)));
        __syncthreads();                       // buf + sInv reuse safe
    }

    // ---- reduce: max over lanes sharing a query row, then across warps ----
    mx0 = fmaxf(mx0, __shfl_xor_sync(~0u, mx0, 1));
    mx0 = fmaxf(mx0, __shfl_xor_sync(~0u, mx0, 2));
    mx1 = fmaxf(mx1, __shfl_xor_sync(~0u, mx1, 1));
    mx1 = fmaxf(mx1, __shfl_xor_sync(~0u, mx1, 2));
    if ((lane & 3) == 0) {
        sW[w * 16 + (lane >> 2)]     = mx0;    // query 16*wq + (lane>>2)
        sW[w * 16 + 8 + (lane >> 2)] = mx1;    // query +8
    }
    __syncthreads();
    if (t < 32) {
        int wq2 = t >> 4, m = t & 15;          // query t = 16*wq2 + m
        float v = fmaxf(fmaxf(sW[wq2 * 16 + m],       sW[(2 + wq2) * 16 + m]),
                        fmaxf(sW[(4 + wq2) * 16 + m], sW[(6 + wq2) * 16 + m]));
#pragma unroll
        for (int o = 16; o; o >>= 1) v += __shfl_xor_sync(~0u, v, o);
        if (t == 0) g_scores[(z * N_ + n) * B_ + b] = v;
    }
}

// ---------------------------------------------------------------------------
// KL(batchmean) over [B, N] — single warp
// ---------------------------------------------------------------------------
__global__ void __launch_bounds__(32) loss_kernel(float* __restrict__ out)
{
    int lane = threadIdx.x;
    float acc = 0.0f;
    for (int bb = lane; bb < B_; bb += 32) {
        float s[N_], tt[N_];
#pragma unroll
        for (int n = 0; n < N_; n++) {
            s[n]  = g_scores[n * B_ + bb];
            tt[n] = g_scores[(N_ + n) * B_ + bb];
        }
        float ms = s[0], mt = tt[0];
#pragma unroll
        for (int n = 1; n < N_; n++) { ms = fmaxf(ms, s[n]); mt = fmaxf(mt, tt[n]); }
        float es = 0.f, et = 0.f;
#pragma unroll
        for (int n = 0; n < N_; n++) { es += expf(s[n] - ms); et += expf(tt[n] - mt); }
        float lses = ms + logf(es);
        float lset = mt + logf(et);
#pragma unroll
        for (int n = 0; n < N_; n++) {
            float lt = tt[n] - lset;
            float ls = s[n]  - lses;
            acc += expf(lt) * (lt - ls);
        }
    }
#pragma unroll
    for (int o = 16; o; o >>= 1) acc += __shfl_xor_sync(~0u, acc, o);
    if (lane == 0) out[0] = acc / (float)B_;
}

// ---------------------------------------------------------------------------
extern "C" void kernel_launch(void* const* d_in, const int* in_sizes, int n_in,
                              void* d_out, int out_size)
{
    const float* q     = (const float*)d_in[0];   // [B,Lq,D]
    const float* dcq   = (const float*)d_in[1];   // [N,B,Ld,D]
    const float* dorig = (const float*)d_in[2];   // [N,B,Ld,D]
    const int*   mask  = (const int*)d_in[3];     // [N,B,Ld]

    cudaFuncSetAttribute(maxsim_mma,
                         cudaFuncAttributeMaxDynamicSharedMemorySize, SMEM_TOTAL);
    dim3 grid(B_, N_, 2);
    maxsim_mma<<<grid, 256, SMEM_TOTAL>>>(q, dcq, dorig, mask);
    loss_kernel<<<1, 32>>>((float*)d_out);
}